// round 16
// baseline (speedup 1.0000x reference)
#include <cuda_runtime.h>
#include <cuda_bf16.h>
#include <cuda_fp16.h>
#include <cstdint>

#define B_WIN   2048
#define NTOK    64
#define DIM     256
#define NHEADS  8
#define QKVDIM  768
#define MROWS   (B_WIN * NTOK)          // 131072
#define SCALE   0.17677669529663687f    // 32^-0.5

// ---------------- scratch (device globals; no cudaMalloc allowed) ----------
#define HEAD_ELEMS (2048ull * 8ull * 64ull * 32ull)
__device__ __half g_qh[HEAD_ELEMS];            // fp16 q (scaled), [bh][n][d]
__device__ __half g_kh[HEAD_ELEMS];            // fp16 k,          [bh][n][d]
__device__ __half g_vth[HEAD_ELEMS];           // fp16 v^T,        [bh][d][n]
__device__ __half g_xh[(size_t)MROWS * DIM];   // fp16 x
__device__ __half g_aoh[(size_t)MROWS * DIM];  // fp16 attention out
__device__ __half g_wqh[QKVDIM * DIM];         // fp16 w_qkv
__device__ __half g_wph[DIM * DIM];            // fp16 w_proj

// ================= helpers ==================================================
__device__ __forceinline__ uint32_t smem_u32(const void* p) {
    uint32_t a;
    asm("{ .reg .u64 t; cvta.to.shared.u64 t, %1; cvt.u32.u64 %0, t; }"
        : "=r"(a) : "l"(p));
    return a;
}

__device__ __forceinline__ void ldsm_x4(uint32_t* r, uint32_t addr) {
    asm volatile("ldmatrix.sync.aligned.m8n8.x4.shared.b16 {%0,%1,%2,%3}, [%4];"
                 : "=r"(r[0]), "=r"(r[1]), "=r"(r[2]), "=r"(r[3]) : "r"(addr));
}

// fp16 k16 mma, fp32 accumulate
__device__ __forceinline__ void mma16816h(float* c, const uint32_t* a, const uint32_t* b) {
    asm volatile("mma.sync.aligned.m16n8k16.row.col.f32.f16.f16.f32 "
                 "{%0,%1,%2,%3}, {%4,%5,%6,%7}, {%8,%9}, {%0,%1,%2,%3};"
                 : "+f"(c[0]), "+f"(c[1]), "+f"(c[2]), "+f"(c[3])
                 : "r"(a[0]), "r"(a[1]), "r"(a[2]), "r"(a[3]),
                   "r"(b[0]), "r"(b[1]));
}

__device__ __forceinline__ uint32_t pack_half2(float x, float y) {
    __half2 t = __floats2half2_rn(x, y);
    return *(uint32_t*)&t;
}

__device__ __forceinline__ void cp16(uint32_t dst, const void* src) {
    asm volatile("cp.async.cg.shared.global [%0], [%1], 16;"
                 :: "r"(dst), "l"(src) : "memory");
}
#define CP_COMMIT() asm volatile("cp.async.commit_group;" ::: "memory")

// ================= fp32 -> fp16 convert =====================================
__global__ void convert_half(const float* __restrict__ src,
                             __half* __restrict__ dst, int n4)
{
    int i = blockIdx.x * blockDim.x + threadIdx.x;
    if (i >= n4) return;
    float4 v = ((const float4*)src)[i];
    ((__half2*)dst)[2*i]   = __floats2half2_rn(v.x, v.y);
    ((__half2*)dst)[2*i+1] = __floats2half2_rn(v.z, v.w);
}

// ================= FP16 GEMM (unchanged from R15) ============================
#define HSTR   40
#define HROWB  80
#define H_A    0
#define H_B    10240
#define HSTAGE 20480
#define HGEMM_SMEM (3 * HSTAGE)     // 61440 bytes

template <int MODE>
__global__ void __launch_bounds__(256, 2)
gemm_fp16(const __half* __restrict__ A, const __half* __restrict__ W,
          const float* __restrict__ bias, float* __restrict__ out)
{
    extern __shared__ char smem[];
    const uint32_t sb = smem_u32(smem);

    const int tid  = threadIdx.x;
    const int lane = tid & 31;
    const int warp = tid >> 5;
    const int wm   = warp >> 1;
    const int wn   = warp & 1;
    const int row0 = blockIdx.y * 128;
    const int col0 = blockIdx.x * 128;

    float acc[2][8][4];
#pragma unroll
    for (int a = 0; a < 2; a++)
#pragma unroll
        for (int b = 0; b < 8; b++)
#pragma unroll
            for (int c = 0; c < 4; c++) acc[a][b][c] = 0.f;

    const int gid = lane >> 2, tig = lane & 3;

    const int lr  = tid >> 2;
    const int lc8 = (tid & 3) * 8;
    const uint32_t so_base = (uint32_t)lr * HROWB + (tid & 3) * 16;

    auto issue = [&](int kc) {
        const uint32_t stb = sb + (kc % 3) * HSTAGE;
        const int k0 = kc * 32;
#pragma unroll
        for (int t = 0; t < 2; t++) {
            const int r = lr + t * 64;
            const uint32_t so = so_base + t * 64 * HROWB;
            cp16(stb + H_A + so, A + (size_t)(row0 + r) * 256 + k0 + lc8);
            cp16(stb + H_B + so, W + (size_t)(col0 + r) * 256 + k0 + lc8);
        }
        CP_COMMIT();
    };

    issue(0);
    issue(1);

    const int a_row  = wm * 32 + (lane & 15);
    const int a_ksel = (lane >> 4) * 8;
    const int b_rowb = wn * 64 + ((lane >> 4) << 3) + (lane & 7);
    const int b_ksel = ((lane >> 3) & 1) << 3;

    for (int kc = 0; kc < 8; kc++) {
        if (kc < 7) {
            asm volatile("cp.async.wait_group 1;" ::: "memory");
        } else {
            asm volatile("cp.async.wait_group 0;" ::: "memory");
        }
        __syncthreads();
        if (kc + 2 < 8) issue(kc + 2);

        const uint32_t sA = sb + (kc % 3) * HSTAGE + H_A;
        const uint32_t sB = sb + (kc % 3) * HSTAGE + H_B;

#pragma unroll
        for (int kk = 0; kk < 32; kk += 16) {
            uint32_t af[2][4];
#pragma unroll
            for (int mt = 0; mt < 2; mt++)
                ldsm_x4(af[mt], sA + (uint32_t)(a_row + mt * 16) * HROWB
                                   + (kk + a_ksel) * 2);
#pragma unroll
            for (int g = 0; g < 4; g++) {
                uint32_t bf[4];
                ldsm_x4(bf, sB + (uint32_t)(b_rowb + g * 16) * HROWB
                               + (kk + b_ksel) * 2);
#pragma unroll
                for (int mt = 0; mt < 2; mt++)
#pragma unroll
                    for (int j = 0; j < 2; j++)
                        mma16816h(acc[mt][g * 2 + j], af[mt], &bf[j * 2]);
            }
        }
    }

    // ---- epilogue -------------------------------------------------------------
#pragma unroll
    for (int mt = 0; mt < 2; mt++)
#pragma unroll
        for (int g = 0; g < 4; g++)
#pragma unroll
            for (int j = 0; j < 2; j++) {
                const int nf = g * 2 + j;
                const int col = col0 + wn * 64 + g * 16 + j * 8 + tig * 2;
                const float2 bv = *(const float2*)(bias + col);
#pragma unroll
                for (int rs = 0; rs < 2; rs++) {
                    const int row = row0 + wm * 32 + mt * 16 + gid + rs * 8;
                    float v0 = acc[mt][nf][rs * 2 + 0] + bv.x;
                    float v1 = acc[mt][nf][rs * 2 + 1] + bv.y;
                    if (MODE == 0) {
                        const int s = col >> 8;
                        if (s == 0) { v0 *= SCALE; v1 *= SCALE; }
                        const int hh = (col >> 5) & 7, d = col & 31;
                        const int b = row >> 6, n = row & 63;
                        const size_t pb = (size_t)(b * 8 + hh) * 2048;
                        if (s == 0) {
                            *(__half2*)(g_qh + pb + n * 32 + d) =
                                __floats2half2_rn(v0, v1);
                        } else if (s == 1) {
                            *(__half2*)(g_kh + pb + n * 32 + d) =
                                __floats2half2_rn(v0, v1);
                        } else {
                            g_vth[pb + (size_t)d * 64 + n]       = __float2half_rn(v0);
                            g_vth[pb + (size_t)(d + 1) * 64 + n] = __float2half_rn(v1);
                        }
                    } else {
                        *(float2*)(out + (size_t)row * 256 + col)
                            = make_float2(v0, v1);
                    }
                }
            }
}

// ================= fp16 attention: ONE WINDOW per CTA (8 heads) =============
// 256 threads, warp = head. q/k/vt staged via cp.async (contiguous 32KB per
// plane per window). Warps independent after one load barrier.
#define AQ_STR 264   // halves per smem row (528B: 4r mod 32 banks, LDSM-clean)
#define AV_STR 72    // halves per smem row (144B)
#define A_BT   0                           // 1800 floats (full bias table)
#define A_Q    7424
#define A_K    (A_Q + 64 * AQ_STR * 2)     // +33792
#define A_V    (A_K + 64 * AQ_STR * 2)     // +33792
#define ATTN_SMEM (A_V + 256 * AV_STR * 2) // +36864 = 111872 bytes

__global__ void __launch_bounds__(256, 2)
attn_mma(const float* __restrict__ mask, const float* __restrict__ bias_table)
{
    extern __shared__ char asmem[];
    const uint32_t sb = smem_u32(asmem);
    float* bt = (float*)(asmem + A_BT);

    const int b    = blockIdx.x;
    const int tid  = threadIdx.x;
    const int h    = tid >> 5;          // warp = head
    const int lane = tid & 31;

    const __half* Qp = g_qh  + (size_t)b * 16384;
    const __half* Kp = g_kh  + (size_t)b * 16384;
    const __half* Vp = g_vth + (size_t)b * 16384;

    // stage q/k/vt: 2048 16B-chunks per plane, 8 per thread
#pragma unroll
    for (int t = 0; t < 8; t++) {
        const int c   = tid + t * 256;
        const int hh  = c >> 8, rem = c & 255;
        const int n   = rem >> 2, d8 = rem & 3;
        const uint32_t qoff = (uint32_t)(n * AQ_STR + hh * 32 + d8 * 8) * 2;
        cp16(sb + A_Q + qoff, Qp + c * 8);
        cp16(sb + A_K + qoff, Kp + c * 8);
        const int d = rem >> 3, n8 = rem & 7;
        const uint32_t voff = (uint32_t)((hh * 32 + d) * AV_STR + n8 * 8) * 2;
        cp16(sb + A_V + voff, Vp + c * 8);
    }
    CP_COMMIT();

    // full bias table (225 x 8 floats) copied once
    for (int t = tid; t < 450; t += 256)
        ((float4*)bt)[t] = ((const float4*)bias_table)[t];

    asm volatile("cp.async.wait_group 0;" ::: "memory");
    __syncthreads();

    const int gid = lane >> 2, tig = lane & 3;
    const int b_row  = ((lane >> 4) << 3) + (lane & 7);
    const int b_ksel = ((lane >> 3) & 1) << 3;
    const float* mrow = mask + (size_t)b * 4096;

    // each warp sweeps its head's 64 rows in 4 groups of 16
#pragma unroll 1
    for (int rg = 0; rg < 4; rg++) {
        // ---- QK^T -----------------------------------------------------------
        float acc[8][4];
#pragma unroll
        for (int nt = 0; nt < 8; nt++)
#pragma unroll
            for (int c = 0; c < 4; c++) acc[nt][c] = 0.f;

        const uint32_t a_rowoff =
            (uint32_t)((rg * 16 + (lane & 15)) * AQ_STR + h * 32 + (lane >> 4) * 8) * 2;

#pragma unroll
        for (int kt = 0; kt < 2; kt++) {
            uint32_t qf[4];
            ldsm_x4(qf, sb + A_Q + a_rowoff + kt * 32);
#pragma unroll
            for (int ng = 0; ng < 4; ng++) {
                uint32_t kf[4];
                const uint32_t off = (uint32_t)((ng * 16 + b_row) * AQ_STR
                                    + h * 32 + kt * 16 + b_ksel) * 2;
                ldsm_x4(kf, sb + A_K + off);
#pragma unroll
                for (int j = 0; j < 2; j++)
                    mma16816h(acc[ng * 2 + j], qf, &kf[j * 2]);
            }
        }

        // ---- bias + mask ------------------------------------------------------
        const int i0 = rg * 16 + gid, i1 = i0 + 8;
        const int yi0 = i0 >> 3, xi0 = i0 & 7;
        const int yi1 = i1 >> 3, xi1 = i1 & 7;
#pragma unroll
        for (int nt = 0; nt < 8; nt++) {
            const int col = nt * 8 + tig * 2;
            const float2 m0 = *(const float2*)(mrow + i0 * 64 + col);
            const float2 m1 = *(const float2*)(mrow + i1 * 64 + col);
            acc[nt][0] += bt[((yi0 - nt + 7) * 15 + (xi0 - tig * 2 + 7)) * 8 + h] + m0.x;
            acc[nt][1] += bt[((yi0 - nt + 7) * 15 + (xi0 - tig * 2 + 6)) * 8 + h] + m0.y;
            acc[nt][2] += bt[((yi1 - nt + 7) * 15 + (xi1 - tig * 2 + 7)) * 8 + h] + m1.x;
            acc[nt][3] += bt[((yi1 - nt + 7) * 15 + (xi1 - tig * 2 + 6)) * 8 + h] + m1.y;
        }

        // ---- softmax ------------------------------------------------------------
        float mx0 = -1e30f, mx1 = -1e30f;
#pragma unroll
        for (int nt = 0; nt < 8; nt++) {
            mx0 = fmaxf(mx0, fmaxf(acc[nt][0], acc[nt][1]));
            mx1 = fmaxf(mx1, fmaxf(acc[nt][2], acc[nt][3]));
        }
        mx0 = fmaxf(mx0, __shfl_xor_sync(0xffffffffu, mx0, 1));
        mx0 = fmaxf(mx0, __shfl_xor_sync(0xffffffffu, mx0, 2));
        mx1 = fmaxf(mx1, __shfl_xor_sync(0xffffffffu, mx1, 1));
        mx1 = fmaxf(mx1, __shfl_xor_sync(0xffffffffu, mx1, 2));

        float sum0 = 0.f, sum1 = 0.f;
#pragma unroll
        for (int nt = 0; nt < 8; nt++) {
            acc[nt][0] = __expf(acc[nt][0] - mx0);
            acc[nt][1] = __expf(acc[nt][1] - mx0);
            acc[nt][2] = __expf(acc[nt][2] - mx1);
            acc[nt][3] = __expf(acc[nt][3] - mx1);
            sum0 += acc[nt][0] + acc[nt][1];
            sum1 += acc[nt][2] + acc[nt][3];
        }
        sum0 += __shfl_xor_sync(0xffffffffu, sum0, 1);
        sum0 += __shfl_xor_sync(0xffffffffu, sum0, 2);
        sum1 += __shfl_xor_sync(0xffffffffu, sum1, 1);
        sum1 += __shfl_xor_sync(0xffffffffu, sum1, 2);
        const float inv0 = 1.f / sum0, inv1 = 1.f / sum1;

        // ---- P fragments (fp16) --------------------------------------------------
        uint32_t pf[4][4];
#pragma unroll
        for (int kt = 0; kt < 4; kt++) {
            pf[kt][0] = pack_half2(acc[kt*2][0] * inv0,   acc[kt*2][1] * inv0);
            pf[kt][1] = pack_half2(acc[kt*2][2] * inv1,   acc[kt*2][3] * inv1);
            pf[kt][2] = pack_half2(acc[kt*2+1][0] * inv0, acc[kt*2+1][1] * inv0);
            pf[kt][3] = pack_half2(acc[kt*2+1][2] * inv1, acc[kt*2+1][3] * inv1);
        }

        // ---- P * V ----------------------------------------------------------------
        float ao[4][4];
#pragma unroll
        for (int dn = 0; dn < 4; dn++)
#pragma unroll
            for (int c = 0; c < 4; c++) ao[dn][c] = 0.f;

#pragma unroll
        for (int kt = 0; kt < 4; kt++) {
#pragma unroll
            for (int g = 0; g < 2; g++) {
                uint32_t vf[4];
                const uint32_t off = (uint32_t)((h * 32 + g * 16 + b_row) * AV_STR
                                    + kt * 16 + b_ksel) * 2;
                ldsm_x4(vf, sb + A_V + off);
#pragma unroll
                for (int j = 0; j < 2; j++)
                    mma16816h(ao[g * 2 + j], pf[kt], &vf[j * 2]);
            }
        }

        // ---- write fp16 ao ----------------------------------------------------------
#pragma unroll
        for (int dn = 0; dn < 4; dn++) {
            const int d = dn * 8 + tig * 2;
#pragma unroll
            for (int rs = 0; rs < 2; rs++) {
                const int row = rs ? i1 : i0;
                const size_t o = ((size_t)b * 64 + row) * DIM + h * 32 + d;
                *(__half2*)(g_aoh + o) =
                    __floats2half2_rn(ao[dn][rs * 2 + 0], ao[dn][rs * 2 + 1]);
            }
        }
    }
}

// ---------------- launch ----------------------------------------------------
extern "C" void kernel_launch(void* const* d_in, const int* in_sizes, int n_in,
                              void* d_out, int out_size)
{
    const float* x          = (const float*)d_in[0]; // (2048,64,256)
    const float* mask       = (const float*)d_in[1]; // (2048,1,64,64)
    const float* w_qkv      = (const float*)d_in[2]; // (768,256)
    const float* b_qkv      = (const float*)d_in[3]; // (768)
    const float* w_proj     = (const float*)d_in[4]; // (256,256)
    const float* b_proj     = (const float*)d_in[5]; // (256)
    const float* bias_table = (const float*)d_in[6]; // (225,8)
    float* out = (float*)d_out;                      // (2048,64,256)

    (void)in_sizes; (void)n_in; (void)out_size;

    __half *xh, *aoh, *wqh, *wph;
    cudaGetSymbolAddress((void**)&xh,  g_xh);
    cudaGetSymbolAddress((void**)&aoh, g_aoh);
    cudaGetSymbolAddress((void**)&wqh, g_wqh);
    cudaGetSymbolAddress((void**)&wph, g_wph);

    cudaFuncSetAttribute(gemm_fp16<0>, cudaFuncAttributeMaxDynamicSharedMemorySize, HGEMM_SMEM);
    cudaFuncSetAttribute(gemm_fp16<1>, cudaFuncAttributeMaxDynamicSharedMemorySize, HGEMM_SMEM);
    cudaFuncSetAttribute(attn_mma,     cudaFuncAttributeMaxDynamicSharedMemorySize, ATTN_SMEM);

    // 0) fp32 -> fp16 converts
    {
        int n4 = (MROWS * DIM) / 4;
        convert_half<<<(n4 + 255) / 256, 256>>>(x, xh, n4);
        int w4 = (QKVDIM * DIM) / 4;
        convert_half<<<(w4 + 255) / 256, 256>>>(w_qkv, wqh, w4);
        int p4 = (DIM * DIM) / 4;
        convert_half<<<(p4 + 255) / 256, 256>>>(w_proj, wph, p4);
    }
    // 1) QKV GEMM (fp16) -> q/k/vt fp16 planes (q pre-scaled)
    {
        dim3 grid(QKVDIM / 128, MROWS / 128);   // 6 x 1024
        gemm_fp16<0><<<grid, 256, HGEMM_SMEM>>>(xh, wqh, b_qkv, nullptr);
    }
    // 2) windowed attention (fp16, one window per CTA) -> g_aoh
    attn_mma<<<B_WIN, 256, ATTN_SMEM>>>(mask, bias_table);
    // 3) output projection (fp16) -> out
    {
        dim3 grid(DIM / 128, MROWS / 128);      // 2 x 1024
        gemm_fp16<1><<<grid, 256, HGEMM_SMEM>>>(aoh, wph, b_proj, out);
    }
}

// round 17
// speedup vs baseline: 1.0853x; 1.0853x over previous
#include <cuda_runtime.h>
#include <cuda_bf16.h>
#include <cuda_fp16.h>
#include <cstdint>

#define B_WIN   2048
#define NTOK    64
#define DIM     256
#define NHEADS  8
#define QKVDIM  768
#define MROWS   (B_WIN * NTOK)          // 131072
#define SCALE   0.17677669529663687f    // 32^-0.5

// ---------------- scratch (device globals; no cudaMalloc allowed) ----------
#define HEAD_ELEMS (2048ull * 8ull * 64ull * 32ull)
__device__ __half g_qh[HEAD_ELEMS];            // fp16 q (scaled), [bh][n][d]
__device__ __half g_kh[HEAD_ELEMS];            // fp16 k,          [bh][n][d]
__device__ __half g_vth[HEAD_ELEMS];           // fp16 v^T,        [bh][d][n]
__device__ __half g_xh[(size_t)MROWS * DIM];   // fp16 x
__device__ __half g_aoh[(size_t)MROWS * DIM];  // fp16 attention out
__device__ __half g_wqh[QKVDIM * DIM];         // fp16 w_qkv
__device__ __half g_wph[DIM * DIM];            // fp16 w_proj

// ================= helpers ==================================================
__device__ __forceinline__ uint32_t smem_u32(const void* p) {
    uint32_t a;
    asm("{ .reg .u64 t; cvta.to.shared.u64 t, %1; cvt.u32.u64 %0, t; }"
        : "=r"(a) : "l"(p));
    return a;
}

__device__ __forceinline__ void ldsm_x4(uint32_t* r, uint32_t addr) {
    asm volatile("ldmatrix.sync.aligned.m8n8.x4.shared.b16 {%0,%1,%2,%3}, [%4];"
                 : "=r"(r[0]), "=r"(r[1]), "=r"(r[2]), "=r"(r[3]) : "r"(addr));
}

// fp16 k16 mma, fp32 accumulate
__device__ __forceinline__ void mma16816h(float* c, const uint32_t* a, const uint32_t* b) {
    asm volatile("mma.sync.aligned.m16n8k16.row.col.f32.f16.f16.f32 "
                 "{%0,%1,%2,%3}, {%4,%5,%6,%7}, {%8,%9}, {%0,%1,%2,%3};"
                 : "+f"(c[0]), "+f"(c[1]), "+f"(c[2]), "+f"(c[3])
                 : "r"(a[0]), "r"(a[1]), "r"(a[2]), "r"(a[3]),
                   "r"(b[0]), "r"(b[1]));
}

__device__ __forceinline__ uint32_t pack_half2(float x, float y) {
    __half2 t = __floats2half2_rn(x, y);
    return *(uint32_t*)&t;
}

__device__ __forceinline__ void cp16(uint32_t dst, const void* src) {
    asm volatile("cp.async.cg.shared.global [%0], [%1], 16;"
                 :: "r"(dst), "l"(src) : "memory");
}
#define CP_COMMIT() asm volatile("cp.async.commit_group;" ::: "memory")

// ================= fused fp32 -> fp16 convert (one launch) ==================
#define XN4 ((MROWS * DIM) / 4)          // 8388608
#define WN4 ((QKVDIM * DIM) / 4)         // 49152
#define PN4 ((DIM * DIM) / 4)            // 16384

__global__ void convert_all(const float* __restrict__ x,
                            const float* __restrict__ wq,
                            const float* __restrict__ wp)
{
    int i = blockIdx.x * blockDim.x + threadIdx.x;
    const float* src;
    __half* dst;
    int j = i;
    if (j < XN4) { src = x; dst = g_xh; }
    else if ((j -= XN4) < WN4) { src = wq; dst = g_wqh; }
    else if ((j -= WN4) < PN4) { src = wp; dst = g_wph; }
    else return;
    float4 v = ((const float4*)src)[j];
    ((__half2*)dst)[2*j]   = __floats2half2_rn(v.x, v.y);
    ((__half2*)dst)[2*j+1] = __floats2half2_rn(v.z, v.w);
}

// ================= FP16 GEMM (unchanged from R15) ============================
#define HSTR   40
#define HROWB  80
#define H_A    0
#define H_B    10240
#define HSTAGE 20480
#define HGEMM_SMEM (3 * HSTAGE)     // 61440 bytes

template <int MODE>
__global__ void __launch_bounds__(256, 2)
gemm_fp16(const __half* __restrict__ A, const __half* __restrict__ W,
          const float* __restrict__ bias, float* __restrict__ out)
{
    extern __shared__ char smem[];
    const uint32_t sb = smem_u32(smem);

    const int tid  = threadIdx.x;
    const int lane = tid & 31;
    const int warp = tid >> 5;
    const int wm   = warp >> 1;
    const int wn   = warp & 1;
    const int row0 = blockIdx.y * 128;
    const int col0 = blockIdx.x * 128;

    float acc[2][8][4];
#pragma unroll
    for (int a = 0; a < 2; a++)
#pragma unroll
        for (int b = 0; b < 8; b++)
#pragma unroll
            for (int c = 0; c < 4; c++) acc[a][b][c] = 0.f;

    const int gid = lane >> 2, tig = lane & 3;

    const int lr  = tid >> 2;
    const int lc8 = (tid & 3) * 8;
    const uint32_t so_base = (uint32_t)lr * HROWB + (tid & 3) * 16;

    auto issue = [&](int kc) {
        const uint32_t stb = sb + (kc % 3) * HSTAGE;
        const int k0 = kc * 32;
#pragma unroll
        for (int t = 0; t < 2; t++) {
            const int r = lr + t * 64;
            const uint32_t so = so_base + t * 64 * HROWB;
            cp16(stb + H_A + so, A + (size_t)(row0 + r) * 256 + k0 + lc8);
            cp16(stb + H_B + so, W + (size_t)(col0 + r) * 256 + k0 + lc8);
        }
        CP_COMMIT();
    };

    issue(0);
    issue(1);

    const int a_row  = wm * 32 + (lane & 15);
    const int a_ksel = (lane >> 4) * 8;
    const int b_rowb = wn * 64 + ((lane >> 4) << 3) + (lane & 7);
    const int b_ksel = ((lane >> 3) & 1) << 3;

    for (int kc = 0; kc < 8; kc++) {
        if (kc < 7) {
            asm volatile("cp.async.wait_group 1;" ::: "memory");
        } else {
            asm volatile("cp.async.wait_group 0;" ::: "memory");
        }
        __syncthreads();
        if (kc + 2 < 8) issue(kc + 2);

        const uint32_t sA = sb + (kc % 3) * HSTAGE + H_A;
        const uint32_t sB = sb + (kc % 3) * HSTAGE + H_B;

#pragma unroll
        for (int kk = 0; kk < 32; kk += 16) {
            uint32_t af[2][4];
#pragma unroll
            for (int mt = 0; mt < 2; mt++)
                ldsm_x4(af[mt], sA + (uint32_t)(a_row + mt * 16) * HROWB
                                   + (kk + a_ksel) * 2);
#pragma unroll
            for (int g = 0; g < 4; g++) {
                uint32_t bf[4];
                ldsm_x4(bf, sB + (uint32_t)(b_rowb + g * 16) * HROWB
                               + (kk + b_ksel) * 2);
#pragma unroll
                for (int mt = 0; mt < 2; mt++)
#pragma unroll
                    for (int j = 0; j < 2; j++)
                        mma16816h(acc[mt][g * 2 + j], af[mt], &bf[j * 2]);
            }
        }
    }

    // ---- epilogue -------------------------------------------------------------
#pragma unroll
    for (int mt = 0; mt < 2; mt++)
#pragma unroll
        for (int g = 0; g < 4; g++)
#pragma unroll
            for (int j = 0; j < 2; j++) {
                const int nf = g * 2 + j;
                const int col = col0 + wn * 64 + g * 16 + j * 8 + tig * 2;
                const float2 bv = *(const float2*)(bias + col);
#pragma unroll
                for (int rs = 0; rs < 2; rs++) {
                    const int row = row0 + wm * 32 + mt * 16 + gid + rs * 8;
                    float v0 = acc[mt][nf][rs * 2 + 0] + bv.x;
                    float v1 = acc[mt][nf][rs * 2 + 1] + bv.y;
                    if (MODE == 0) {
                        const int s = col >> 8;
                        if (s == 0) { v0 *= SCALE; v1 *= SCALE; }
                        const int hh = (col >> 5) & 7, d = col & 31;
                        const int b = row >> 6, n = row & 63;
                        const size_t pb = (size_t)(b * 8 + hh) * 2048;
                        if (s == 0) {
                            *(__half2*)(g_qh + pb + n * 32 + d) =
                                __floats2half2_rn(v0, v1);
                        } else if (s == 1) {
                            *(__half2*)(g_kh + pb + n * 32 + d) =
                                __floats2half2_rn(v0, v1);
                        } else {
                            g_vth[pb + (size_t)d * 64 + n]       = __float2half_rn(v0);
                            g_vth[pb + (size_t)(d + 1) * 64 + n] = __float2half_rn(v1);
                        }
                    } else {
                        *(float2*)(out + (size_t)row * 256 + col)
                            = make_float2(v0, v1);
                    }
                }
            }
}

// ================= fp16 attention (R15 shape + cp.async staging) =============
#define QSTR 40
#define VSTR 72

__global__ void __launch_bounds__(128)
attn_mma(const float* __restrict__ mask, const float* __restrict__ bias_table)
{
    const int bh = blockIdx.x;
    const int b  = bh >> 3;
    const int h  = bh & 7;

    __shared__ __half sQ[64 * QSTR];
    __shared__ __half sK[64 * QSTR];
    __shared__ __half sV[32 * VSTR];
    __shared__ float bt[228];

    const int tid  = threadIdx.x;
    const int warp = tid >> 5;
    const int lane = tid & 31;

    const __half* Qp = g_qh  + (size_t)bh * 2048;
    const __half* Kp = g_kh  + (size_t)bh * 2048;
    const __half* Vp = g_vth + (size_t)bh * 2048;

    const uint32_t sQb = smem_u32(sQ), sKb = smem_u32(sK), sVb = smem_u32(sV);

    // async stage: 256 16B-chunks per plane, 2 per thread, 6 cp.async/thread
#pragma unroll
    for (int t = 0; t < 2; t++) {
        const int c = tid + t * 128;
        const int qr = c >> 2, qc = (c & 3) * 8;
        cp16(sQb + (uint32_t)(qr * QSTR + qc) * 2, Qp + c * 8);
        cp16(sKb + (uint32_t)(qr * QSTR + qc) * 2, Kp + c * 8);
        const int vr = c >> 3, vc = (c & 7) * 8;
        cp16(sVb + (uint32_t)(vr * VSTR + vc) * 2, Vp + c * 8);
    }
    CP_COMMIT();

    for (int t = tid; t < 225; t += 128) bt[t] = bias_table[t * NHEADS + h];

    asm volatile("cp.async.wait_group 0;" ::: "memory");
    __syncthreads();

    const int gid = lane >> 2, tig = lane & 3;
    const int a_rowoff = (warp * 16 + (lane & 15)) * QSTR + (lane >> 4) * 8;
    const int b_row    = ((lane >> 4) << 3) + (lane & 7);
    const int b_ksel   = ((lane >> 3) & 1) << 3;

    // ---- QK^T -----------------------------------------------------------------
    float acc[8][4];
#pragma unroll
    for (int nt = 0; nt < 8; nt++)
#pragma unroll
        for (int c = 0; c < 4; c++) acc[nt][c] = 0.f;

#pragma unroll
    for (int kt = 0; kt < 2; kt++) {
        uint32_t qf[4];
        ldsm_x4(qf, smem_u32(sQ + a_rowoff + kt * 16));
#pragma unroll
        for (int ng = 0; ng < 4; ng++) {
            uint32_t kf[4];
            const int off = (ng * 16 + b_row) * QSTR + kt * 16 + b_ksel;
            ldsm_x4(kf, smem_u32(sK + off));
#pragma unroll
            for (int j = 0; j < 2; j++)
                mma16816h(acc[ng * 2 + j], qf, &kf[j * 2]);
        }
    }

    // ---- bias + mask ------------------------------------------------------------
    const int i0 = warp * 16 + gid, i1 = i0 + 8;
    const int yi0 = i0 >> 3, xi0 = i0 & 7;
    const int yi1 = i1 >> 3, xi1 = i1 & 7;
    const float* mrow = mask + (size_t)b * 4096;
#pragma unroll
    for (int nt = 0; nt < 8; nt++) {
        const int col = nt * 8 + tig * 2;
        const float2 m0 = *(const float2*)(mrow + i0 * 64 + col);
        const float2 m1 = *(const float2*)(mrow + i1 * 64 + col);
        acc[nt][0] += bt[(yi0 - nt + 7) * 15 + (xi0 - tig * 2 + 7)] + m0.x;
        acc[nt][1] += bt[(yi0 - nt + 7) * 15 + (xi0 - tig * 2 + 6)] + m0.y;
        acc[nt][2] += bt[(yi1 - nt + 7) * 15 + (xi1 - tig * 2 + 7)] + m1.x;
        acc[nt][3] += bt[(yi1 - nt + 7) * 15 + (xi1 - tig * 2 + 6)] + m1.y;
    }

    // ---- softmax -------------------------------------------------------------------
    float mx0 = -1e30f, mx1 = -1e30f;
#pragma unroll
    for (int nt = 0; nt < 8; nt++) {
        mx0 = fmaxf(mx0, fmaxf(acc[nt][0], acc[nt][1]));
        mx1 = fmaxf(mx1, fmaxf(acc[nt][2], acc[nt][3]));
    }
    mx0 = fmaxf(mx0, __shfl_xor_sync(0xffffffffu, mx0, 1));
    mx0 = fmaxf(mx0, __shfl_xor_sync(0xffffffffu, mx0, 2));
    mx1 = fmaxf(mx1, __shfl_xor_sync(0xffffffffu, mx1, 1));
    mx1 = fmaxf(mx1, __shfl_xor_sync(0xffffffffu, mx1, 2));

    float sum0 = 0.f, sum1 = 0.f;
#pragma unroll
    for (int nt = 0; nt < 8; nt++) {
        acc[nt][0] = __expf(acc[nt][0] - mx0);
        acc[nt][1] = __expf(acc[nt][1] - mx0);
        acc[nt][2] = __expf(acc[nt][2] - mx1);
        acc[nt][3] = __expf(acc[nt][3] - mx1);
        sum0 += acc[nt][0] + acc[nt][1];
        sum1 += acc[nt][2] + acc[nt][3];
    }
    sum0 += __shfl_xor_sync(0xffffffffu, sum0, 1);
    sum0 += __shfl_xor_sync(0xffffffffu, sum0, 2);
    sum1 += __shfl_xor_sync(0xffffffffu, sum1, 1);
    sum1 += __shfl_xor_sync(0xffffffffu, sum1, 2);
    const float inv0 = 1.f / sum0, inv1 = 1.f / sum1;

    // ---- P fragments (fp16) ----------------------------------------------------------
    uint32_t pf[4][4];
#pragma unroll
    for (int kt = 0; kt < 4; kt++) {
        pf[kt][0] = pack_half2(acc[kt*2][0] * inv0,   acc[kt*2][1] * inv0);
        pf[kt][1] = pack_half2(acc[kt*2][2] * inv1,   acc[kt*2][3] * inv1);
        pf[kt][2] = pack_half2(acc[kt*2+1][0] * inv0, acc[kt*2+1][1] * inv0);
        pf[kt][3] = pack_half2(acc[kt*2+1][2] * inv1, acc[kt*2+1][3] * inv1);
    }

    // ---- P * V ------------------------------------------------------------------------
    float ao[4][4];
#pragma unroll
    for (int dn = 0; dn < 4; dn++)
#pragma unroll
        for (int c = 0; c < 4; c++) ao[dn][c] = 0.f;

#pragma unroll
    for (int kt = 0; kt < 4; kt++) {
#pragma unroll
        for (int g = 0; g < 2; g++) {
            uint32_t vf[4];
            const int off = (g * 16 + b_row) * VSTR + kt * 16 + b_ksel;
            ldsm_x4(vf, smem_u32(sV + off));
#pragma unroll
            for (int j = 0; j < 2; j++)
                mma16816h(ao[g * 2 + j], pf[kt], &vf[j * 2]);
        }
    }

    // ---- epilogue ----------------------------------------------------------------------
#pragma unroll
    for (int dn = 0; dn < 4; dn++) {
        const int d = dn * 8 + tig * 2;
#pragma unroll
        for (int rs = 0; rs < 2; rs++) {
            const int row = rs ? i1 : i0;
            const size_t o = ((size_t)b * 64 + row) * DIM + h * 32 + d;
            *(__half2*)(g_aoh + o) =
                __floats2half2_rn(ao[dn][rs * 2 + 0], ao[dn][rs * 2 + 1]);
        }
    }
}

// ---------------- launch ----------------------------------------------------
extern "C" void kernel_launch(void* const* d_in, const int* in_sizes, int n_in,
                              void* d_out, int out_size)
{
    const float* x          = (const float*)d_in[0]; // (2048,64,256)
    const float* mask       = (const float*)d_in[1]; // (2048,1,64,64)
    const float* w_qkv      = (const float*)d_in[2]; // (768,256)
    const float* b_qkv      = (const float*)d_in[3]; // (768)
    const float* w_proj     = (const float*)d_in[4]; // (256,256)
    const float* b_proj     = (const float*)d_in[5]; // (256)
    const float* bias_table = (const float*)d_in[6]; // (225,8)
    float* out = (float*)d_out;                      // (2048,64,256)

    (void)in_sizes; (void)n_in; (void)out_size;

    __half *xh, *aoh, *wqh, *wph;
    cudaGetSymbolAddress((void**)&xh,  g_xh);
    cudaGetSymbolAddress((void**)&aoh, g_aoh);
    cudaGetSymbolAddress((void**)&wqh, g_wqh);
    cudaGetSymbolAddress((void**)&wph, g_wph);

    cudaFuncSetAttribute(gemm_fp16<0>, cudaFuncAttributeMaxDynamicSharedMemorySize, HGEMM_SMEM);
    cudaFuncSetAttribute(gemm_fp16<1>, cudaFuncAttributeMaxDynamicSharedMemorySize, HGEMM_SMEM);

    // 0) fused fp32 -> fp16 converts (one launch)
    {
        int total = XN4 + WN4 + PN4;
        convert_all<<<(total + 255) / 256, 256>>>(x, w_qkv, w_proj);
    }
    // 1) QKV GEMM (fp16) -> q/k/vt fp16 planes (q pre-scaled)
    {
        dim3 grid(QKVDIM / 128, MROWS / 128);   // 6 x 1024
        gemm_fp16<0><<<grid, 256, HGEMM_SMEM>>>(xh, wqh, b_qkv, nullptr);
    }
    // 2) windowed attention (fp16, R15 shape + cp.async) -> g_aoh
    attn_mma<<<B_WIN * NHEADS, 128>>>(mask, bias_table);
    // 3) output projection (fp16) -> out
    {
        dim3 grid(DIM / 128, MROWS / 128);      // 2 x 1024
        gemm_fp16<1><<<grid, 256, HGEMM_SMEM>>>(aoh, wph, b_proj, out);
    }
}